// round 12
// baseline (speedup 1.0000x reference)
#include <cuda_runtime.h>
#include <cuda_fp16.h>
#include <math.h>
#include <stdint.h>
#include <mma.h>

using namespace nvcuda;

// ---------------- problem constants ----------------
#define DIMC   384
#define HEADS  6
#define HD     64
#define HIDDEN 1536
#define BATCH  4
#define NX     2048
#define NY     256
#define MTOK   2304
#define TTOK   (BATCH*MTOK)          // 9216
#define QKVN   (3*DIMC)              // 1152
#define ATT_SCALE 0.125f
#define LN_EPS 1e-5f

#define HTS 72                       // half row stride (elements); 144B

// attention smem: K/V double buffers only
#define SMEM_ATTN5 (4*64*HTS*2)      // 36,864 B

// GEMM v2 smem layout: block 128x128, A/W tiles 128x64 halves, double buffered
#define GT_BYTES (128*HTS*2)               // 18,432 per tile buffer
#define GOFF_A0  0
#define GOFF_A1  (GOFF_A0 + GT_BYTES)
#define GOFF_W0  (GOFF_A1 + GT_BYTES)
#define GOFF_W1  (GOFF_W0 + GT_BYTES)
#define GOFF_CT  (GOFF_W1 + GT_BYTES)      // 73,728; fp32 8*320
#define SMEM_GEMM (GOFF_CT + 8*320*4)      // 83,968 B

#define NSPLIT 4
#define KSPLIT (MTOK/NSPLIT)         // 576
#define QBY    (NY/128)              // 2

// weight scratch offsets (half weights)
#define OFF_QKVW 0
#define OFF_PROJW (QKVN*DIMC)
#define OFF_FC1W  (OFF_PROJW + DIMC*DIMC)
#define OFF_FC2W  (OFF_FC1W + HIDDEN*DIMC)
#define W_TOTAL   (OFF_FC2W + DIMC*HIDDEN)

// ---------------- scratch ----------------
__device__ __half g_catln[TTOK*DIMC];
__device__ __half g_qkvh [TTOK*QKVN];
__device__ __half g_attno[TTOK*DIMC];
__device__ __half g_ln2  [TTOK*DIMC];
__device__ __half g_fc1  [TTOK*HIDDEN];
__device__ __half g_wrnd [W_TOTAL];
__device__ float  g_pO   [BATCH*HEADS*QBY*NSPLIT*128*64];
__device__ float  g_pL   [BATCH*HEADS*QBY*NSPLIT*128];

// ---------------- helpers ----------------
__device__ __forceinline__ void cp16(void* smem, const void* gmem) {
    uint32_t s = (uint32_t)__cvta_generic_to_shared(smem);
    asm volatile("cp.async.cg.shared.global [%0], [%1], 16;" :: "r"(s), "l"(gmem));
}
#define CP_COMMIT() asm volatile("cp.async.commit_group;")
#define CP_WAIT0()  asm volatile("cp.async.wait_group 0;")

__device__ __forceinline__ void mma16816(float* c, const uint32_t* a, uint32_t b0, uint32_t b1) {
    asm volatile(
        "mma.sync.aligned.m16n8k16.row.col.f32.f16.f16.f32 "
        "{%0,%1,%2,%3},{%4,%5,%6,%7},{%8,%9},{%0,%1,%2,%3};"
        : "+f"(c[0]), "+f"(c[1]), "+f"(c[2]), "+f"(c[3])
        : "r"(a[0]), "r"(a[1]), "r"(a[2]), "r"(a[3]), "r"(b0), "r"(b1));
}
__device__ __forceinline__ uint32_t pack_h2(float x, float y) {
    __half2 h = __floats2half2_rn(x, y);
    return *(uint32_t*)&h;
}

// ---------------- weight pre-rounding to fp16 ----------------
__global__ void round_weights(const float* __restrict__ qkvw, const float* __restrict__ projw,
                              const float* __restrict__ fc1w, const float* __restrict__ fc2w,
                              __half* __restrict__ dst)
{
    int stride = gridDim.x * blockDim.x;
    int i0 = blockIdx.x * blockDim.x + threadIdx.x;
    for (int i = i0; i < QKVN*DIMC;   i += stride) dst[OFF_QKVW + i]  = __float2half(qkvw[i]);
    for (int i = i0; i < DIMC*DIMC;   i += stride) dst[OFF_PROJW + i] = __float2half(projw[i]);
    for (int i = i0; i < HIDDEN*DIMC; i += stride) dst[OFF_FC1W + i]  = __float2half(fc1w[i]);
    for (int i = i0; i < DIMC*HIDDEN; i += stride) dst[OFF_FC2W + i]  = __float2half(fc2w[i]);
}

// ---------------- LayerNorm: 1 warp per token ----------------
__global__ void __launch_bounds__(256) ln_fast(
    const float* __restrict__ px, const float* __restrict__ py,
    const float* __restrict__ w,  const float* __restrict__ bsh,
    __half* __restrict__ out)
{
    int wi = threadIdx.x >> 5, lane = threadIdx.x & 31;
    int t  = blockIdx.x*8 + wi;
    int bb = t / MTOK, pos = t - bb*MTOK;
    const float* src = (pos < NX)
        ? px + (size_t)(bb*NX + pos)*DIMC
        : py + (size_t)(bb*NY + pos - NX)*DIMC;

    float4 v[3];
    float s = 0.f, sq = 0.f;
    #pragma unroll
    for (int i = 0; i < 3; i++) {
        v[i] = ((const float4*)src)[lane + 32*i];
        s  += v[i].x + v[i].y + v[i].z + v[i].w;
        sq += v[i].x*v[i].x + v[i].y*v[i].y + v[i].z*v[i].z + v[i].w*v[i].w;
    }
    #pragma unroll
    for (int o = 16; o; o >>= 1) {
        s  += __shfl_xor_sync(0xffffffffu, s,  o);
        sq += __shfl_xor_sync(0xffffffffu, sq, o);
    }
    float mean = s * (1.0f/DIMC);
    float inv  = rsqrtf(sq * (1.0f/DIMC) - mean*mean + LN_EPS);

    uint32_t* op = (uint32_t*)(out + (size_t)t*DIMC);
    #pragma unroll
    for (int i = 0; i < 3; i++) {
        int idx4 = lane + 32*i;
        float4 ww = ((const float4*)w)[idx4];
        float4 bb4 = ((const float4*)bsh)[idx4];
        op[2*idx4]   = pack_h2((v[i].x-mean)*inv*ww.x + bb4.x, (v[i].y-mean)*inv*ww.y + bb4.y);
        op[2*idx4+1] = pack_h2((v[i].z-mean)*inv*ww.z + bb4.z, (v[i].w-mean)*inv*ww.w + bb4.w);
    }
}

// ---------------- per-element epilogue ----------------
template<int EPI>
__device__ __forceinline__ void epi_elem(int m, int n, float v, int N,
    const float* __restrict__ bias, __half* __restrict__ C,
    const float* __restrict__ resx, const float* __restrict__ resy,
    float* __restrict__ outx, float* __restrict__ outy)
{
    if (EPI == 0) { C[(size_t)m*N + n] = __float2half(v); return; }
    float bv = bias[n];
    if (EPI == 2) {
        float x = v + bv;
        C[(size_t)m*N + n] = __float2half(0.5f * x * (1.0f + erff(x * 0.70710678118654752f)));
        return;
    }
    int bb  = m / MTOK;
    int pos = m - bb * MTOK;
    if (pos < NX) {
        size_t idx = ((size_t)(bb*NX + pos))*DIMC + n;
        float r = (EPI == 1) ? resx[idx] : outx[idx];
        outx[idx] = v + bv + r;
    } else {
        size_t idx = ((size_t)(bb*NY + pos - NX))*DIMC + n;
        float r = (EPI == 1) ? resy[idx] : outy[idx];
        outy[idx] = v + bv + r;
    }
}

// ---------------- fp16 wmma GEMM v2: block 128x128, warp tile 32x64 ----------------
// C[M,N] = A[M,K] * W[N,K]^T. 8 warps (4x2), k-tile 64, cp.async double-buffered.
template<int EPI>
__global__ void __launch_bounds__(256, 2) gemm_fp16(
    const __half* __restrict__ A, const __half* __restrict__ W,
    const float* __restrict__ bias, __half* __restrict__ C,
    int M, int N, int K,
    const float* __restrict__ resx, const float* __restrict__ resy,
    float* __restrict__ outx, float* __restrict__ outy)
{
    extern __shared__ __align__(16) char dsm[];
    __half* Ab[2] = { (__half*)(dsm + GOFF_A0), (__half*)(dsm + GOFF_A1) };
    __half* Wb[2] = { (__half*)(dsm + GOFF_W0), (__half*)(dsm + GOFF_W1) };
    float*  Ct    = (float*)(dsm + GOFF_CT);

    int tid = threadIdx.x;
    int w = tid >> 5, lane = tid & 31;
    int wm = w >> 1, wn = w & 1;               // 4x2 warp grid
    int m0 = blockIdx.y << 7;
    int n0 = blockIdx.x << 7;

    wmma::fragment<wmma::accumulator, 16, 16, 16, float> acc[2][4];
    #pragma unroll
    for (int i = 0; i < 2; i++)
        #pragma unroll
        for (int j = 0; j < 4; j++) wmma::fill_fragment(acc[i][j], 0.0f);

    int T = K >> 6;
    // stage tile 0: A 128x64, W 128x64 (each: 1024 16B-chunks / 256 thr = 4)
    {
        #pragma unroll
        for (int i = 0; i < 4; i++) {
            int idx = tid + i*256;
            int row = idx >> 3, c8 = (idx & 7) << 3;
            cp16(Ab[0] + row*HTS + c8, A + (size_t)(m0+row)*K + c8);
            cp16(Wb[0] + row*HTS + c8, W + (size_t)(n0+row)*K + c8);
        }
        CP_COMMIT();
    }

    for (int t = 0; t < T; t++) {
        CP_WAIT0();
        __syncthreads();
        if (t + 1 < T) {
            int k0 = (t+1) << 6;
            __half* An = Ab[(t+1)&1];
            __half* Wn = Wb[(t+1)&1];
            #pragma unroll
            for (int i = 0; i < 4; i++) {
                int idx = tid + i*256;
                int row = idx >> 3, c8 = (idx & 7) << 3;
                cp16(An + row*HTS + c8, A + (size_t)(m0+row)*K + k0 + c8);
                cp16(Wn + row*HTS + c8, W + (size_t)(n0+row)*K + k0 + c8);
            }
            CP_COMMIT();
        }
        __half* Ac = Ab[t&1];
        __half* Wc = Wb[t&1];
        #pragma unroll
        for (int ks = 0; ks < 4; ks++) {
            int kb = ks << 4;
            wmma::fragment<wmma::matrix_a, 16, 16, 16, __half, wmma::row_major> af[2];
            wmma::fragment<wmma::matrix_b, 16, 16, 16, __half, wmma::col_major> bf[4];
            wmma::load_matrix_sync(af[0], Ac + (wm*32     )*HTS + kb, HTS);
            wmma::load_matrix_sync(af[1], Ac + (wm*32 + 16)*HTS + kb, HTS);
            #pragma unroll
            for (int j = 0; j < 4; j++)
                wmma::load_matrix_sync(bf[j], Wc + (wn*64 + j*16)*HTS + kb, HTS);
            #pragma unroll
            for (int i = 0; i < 2; i++)
                #pragma unroll
                for (int j = 0; j < 4; j++)
                    wmma::mma_sync(acc[i][j], af[i], bf[j], acc[i][j]);
        }
        __syncthreads();
    }

    float* myCt = Ct + w*320;
    #pragma unroll
    for (int i = 0; i < 2; i++) {
        #pragma unroll
        for (int j = 0; j < 4; j++) {
            wmma::store_matrix_sync(myCt, acc[i][j], 20, wmma::mem_row_major);
            __syncwarp();
            int r  = lane >> 1;
            int cb = (lane & 1) << 3;
            int mg = m0 + wm*32 + i*16 + r;
            int ng = n0 + wn*64 + j*16 + cb;
            #pragma unroll
            for (int q = 0; q < 8; q++)
                epi_elem<EPI>(mg, ng + q, myCt[r*20 + cb + q], N, bias, C, resx, resy, outx, outy);
            __syncwarp();
        }
    }
}

// ---------------- attention v5 (R11-proven): raw PTX mma, register S/P/O ----------------
template<bool SPLIT>
__global__ void __launch_bounds__(256, 2) attn_v5(
    const __half* __restrict__ qkvh, __half* __restrict__ attno,
    float* __restrict__ pO, float* __restrict__ pL,
    int q_base, int klen)
{
    extern __shared__ __align__(16) char dsm[];
    __half* Kb[2] = { (__half*)(dsm),               (__half*)(dsm + 64*HTS*2)   };
    __half* Vb[2] = { (__half*)(dsm + 2*64*HTS*2),  (__half*)(dsm + 3*64*HTS*2) };

    int tid = threadIdx.x, w = tid >> 5, lane = tid & 31;
    int g = lane >> 2, t = lane & 3;
    int h = blockIdx.y, b = blockIdx.z;
    int qb, sp;
    if (SPLIT) { qb = blockIdx.x >> 2; sp = blockIdx.x & 3; }
    else       { qb = blockIdx.x;      sp = 0; }
    int q0   = q_base + (qb << 7);
    int koff = SPLIT ? sp * klen : 0;

    uint32_t qa[4][4];
    {
        const __half* qrow0 = qkvh + (size_t)(b*MTOK + q0 + w*16 + g)*QKVN + h*HD;
        const __half* qrow1 = qrow0 + 8*QKVN;
        #pragma unroll
        for (int c = 0; c < 4; c++) {
            qa[c][0] = *(const uint32_t*)(qrow0 + 16*c     + 2*t);
            qa[c][1] = *(const uint32_t*)(qrow1 + 16*c     + 2*t);
            qa[c][2] = *(const uint32_t*)(qrow0 + 16*c + 8 + 2*t);
            qa[c][3] = *(const uint32_t*)(qrow1 + 16*c + 8 + 2*t);
        }
    }

    float oac[8][4];
    #pragma unroll
    for (int j = 0; j < 8; j++)
        #pragma unroll
        for (int c = 0; c < 4; c++) oac[j][c] = 0.f;
    float rs0 = 0.f, rs1 = 0.f;

    const __half* kbase = qkvh + ((size_t)b*MTOK)*QKVN + DIMC   + h*HD;
    const __half* vbase = qkvh + ((size_t)b*MTOK)*QKVN + 2*DIMC + h*HD;

    int T = klen >> 6;
    {
        #pragma unroll
        for (int i = 0; i < 2; i++) {
            int idx = tid + i*256;
            int row = idx >> 3, c8 = (idx & 7) << 3;
            cp16(Kb[0] + row*HTS + c8, kbase + (size_t)(koff+row)*QKVN + c8);
            cp16(Vb[0] + row*HTS + c8, vbase + (size_t)(koff+row)*QKVN + c8);
        }
        CP_COMMIT();
    }

    for (int it = 0; it < T; it++) {
        CP_WAIT0();
        __syncthreads();
        if (it + 1 < T) {
            int kt = koff + ((it+1) << 6);
            __half* Kn = Kb[(it+1)&1];
            __half* Vn = Vb[(it+1)&1];
            #pragma unroll
            for (int i = 0; i < 2; i++) {
                int idx = tid + i*256;
                int row = idx >> 3, c8 = (idx & 7) << 3;
                cp16(Kn + row*HTS + c8, kbase + (size_t)(kt+row)*QKVN + c8);
                cp16(Vn + row*HTS + c8, vbase + (size_t)(kt+row)*QKVN + c8);
            }
            CP_COMMIT();
        }
        const uint32_t* Ku = (const uint32_t*)Kb[it&1];
        __half* Vs = Vb[it&1];

        uint32_t ph[8][2];
        #pragma unroll
        for (int j = 0; j < 8; j++) {
            float sc[4] = {0.f, 0.f, 0.f, 0.f};
            int krow = (8*j + g)*36 + t;
            #pragma unroll
            for (int c = 0; c < 4; c++)
                mma16816(sc, qa[c], Ku[krow + 8*c], Ku[krow + 8*c + 4]);
            float e0 = __expf(sc[0]*ATT_SCALE);
            float e1 = __expf(sc[1]*ATT_SCALE);
            float e2 = __expf(sc[2]*ATT_SCALE);
            float e3 = __expf(sc[3]*ATT_SCALE);
            rs0 += e0 + e1;
            rs1 += e2 + e3;
            ph[j][0] = pack_h2(e0, e1);
            ph[j][1] = pack_h2(e2, e3);
        }

        #pragma unroll
        for (int kc = 0; kc < 4; kc++) {
            uint32_t af[4] = { ph[2*kc][0], ph[2*kc][1], ph[2*kc+1][0], ph[2*kc+1][1] };
            #pragma unroll
            for (int jd = 0; jd < 8; jd += 2) {
                int row = 16*kc + ((lane >> 3) & 1)*8 + (lane & 7);
                int col = 8*jd + ((lane >> 4) << 3);
                uint32_t addr = (uint32_t)__cvta_generic_to_shared(Vs + row*HTS + col);
                uint32_t v0, v1, v2, v3;
                asm volatile(
                    "ldmatrix.sync.aligned.m8n8.x4.trans.shared.b16 {%0,%1,%2,%3}, [%4];"
                    : "=r"(v0), "=r"(v1), "=r"(v2), "=r"(v3) : "r"(addr));
                mma16816(oac[jd],   af, v0, v1);
                mma16816(oac[jd+1], af, v2, v3);
            }
        }
    }

    rs0 += __shfl_xor_sync(0xffffffffu, rs0, 1);
    rs0 += __shfl_xor_sync(0xffffffffu, rs0, 2);
    rs1 += __shfl_xor_sync(0xffffffffu, rs1, 1);
    rs1 += __shfl_xor_sync(0xffffffffu, rs1, 2);

    if (SPLIT) {
        int pidx = ((b*HEADS + h)*QBY + qb)*NSPLIT + sp;
        float* dst0 = pO + (size_t)pidx*(128*64) + (w*16 + g)*64;
        float* dst1 = dst0 + 8*64;
        #pragma unroll
        for (int jd = 0; jd < 8; jd++) {
            int col = 8*jd + 2*t;
            *(float2*)(dst0 + col) = make_float2(oac[jd][0], oac[jd][1]);
            *(float2*)(dst1 + col) = make_float2(oac[jd][2], oac[jd][3]);
        }
        if (t == 0) {
            pL[pidx*128 + w*16 + g]     = rs0;
            pL[pidx*128 + w*16 + g + 8] = rs1;
        }
    } else {
        float inv0 = 1.f / rs0;
        float inv1 = 1.f / rs1;
        __half* orow0 = attno + (size_t)(b*MTOK + q0 + w*16 + g)*DIMC + h*HD;
        __half* orow1 = orow0 + 8*DIMC;
        #pragma unroll
        for (int jd = 0; jd < 8; jd++) {
            int col = 8*jd + 2*t;
            *(uint32_t*)(orow0 + col) = pack_h2(oac[jd][0]*inv0, oac[jd][1]*inv0);
            *(uint32_t*)(orow1 + col) = pack_h2(oac[jd][2]*inv1, oac[jd][3]*inv1);
        }
    }
}

// ---------------- merge split-K partials ----------------
__global__ void __launch_bounds__(128) merge_attn(
    const float* __restrict__ pO, const float* __restrict__ pL,
    __half* __restrict__ attno)
{
    int qb = blockIdx.x, h = blockIdx.y, b = blockIdx.z;
    int r = threadIdx.x;
    int base = ((b*HEADS + h)*QBY + qb)*NSPLIT;

    float L = 0.f;
    #pragma unroll
    for (int s = 0; s < NSPLIT; s++) L += pL[(base+s)*128 + r];
    float inv = 1.f / L;

    int qi = NX + (qb << 7) + r;
    __half* op = attno + ((size_t)(b*MTOK + qi))*DIMC + h*HD;
    #pragma unroll 4
    for (int c = 0; c < 64; c++) {
        float o = 0.f;
        #pragma unroll
        for (int s = 0; s < NSPLIT; s++)
            o += pO[(size_t)(base+s)*(128*64) + r*64 + c];
        op[c] = __float2half(o * inv);
    }
}

// ---------------- launch ----------------
extern "C" void kernel_launch(void* const* d_in, const int* in_sizes, int n_in,
                              void* d_out, int out_size)
{
    const float* x     = (const float*)d_in[0];
    const float* y     = (const float*)d_in[1];
    const float* n1w   = (const float*)d_in[2];
    const float* n1b   = (const float*)d_in[3];
    const float* n2w   = (const float*)d_in[4];
    const float* n2b   = (const float*)d_in[5];
    const float* qkvw  = (const float*)d_in[6];
    const float* projw = (const float*)d_in[7];
    const float* projb = (const float*)d_in[8];
    const float* fc1w  = (const float*)d_in[9];
    const float* fc1bb = (const float*)d_in[10];
    const float* fc2w  = (const float*)d_in[11];
    const float* fc2b  = (const float*)d_in[12];
    (void)in_sizes; (void)n_in; (void)out_size;

    float* outx = (float*)d_out;
    float* outy = outx + (size_t)BATCH*NX*DIMC;

    __half *catln, *qkvh, *attno, *ln2o, *fc1o, *wrnd;
    float *pO, *pL;
    cudaGetSymbolAddress((void**)&catln, g_catln);
    cudaGetSymbolAddress((void**)&qkvh,  g_qkvh);
    cudaGetSymbolAddress((void**)&attno, g_attno);
    cudaGetSymbolAddress((void**)&ln2o,  g_ln2);
    cudaGetSymbolAddress((void**)&fc1o,  g_fc1);
    cudaGetSymbolAddress((void**)&wrnd,  g_wrnd);
    cudaGetSymbolAddress((void**)&pO,    g_pO);
    cudaGetSymbolAddress((void**)&pL,    g_pL);

    cudaFuncSetAttribute(gemm_fp16<0>, cudaFuncAttributeMaxDynamicSharedMemorySize, SMEM_GEMM);
    cudaFuncSetAttribute(gemm_fp16<1>, cudaFuncAttributeMaxDynamicSharedMemorySize, SMEM_GEMM);
    cudaFuncSetAttribute(gemm_fp16<2>, cudaFuncAttributeMaxDynamicSharedMemorySize, SMEM_GEMM);
    cudaFuncSetAttribute(gemm_fp16<3>, cudaFuncAttributeMaxDynamicSharedMemorySize, SMEM_GEMM);

    // 0) pre-round weights to fp16
    round_weights<<<256, 256>>>(qkvw, projw, fc1w, fc2w, wrnd);
    // 1) LN1 over concat(x, y)
    ln_fast<<<TTOK/8, 256>>>(x, y, n1w, n1b, catln);
    // 2) fused QKV GEMM (block 128x128)
    gemm_fp16<0><<<dim3(QKVN/128, TTOK/128), 256, SMEM_GEMM>>>(catln, wrnd + OFF_QKVW, nullptr, qkvh,
        TTOK, QKVN, DIMC, nullptr, nullptr, nullptr, nullptr);
    // 3) x self-attention
    attn_v5<false><<<dim3(NX/128, HEADS, BATCH), 256, SMEM_ATTN5>>>(qkvh, attno, nullptr, nullptr, 0, NX);
    // 4) y cross-attention: split-K x4 + merge
    attn_v5<true><<<dim3(QBY*NSPLIT, HEADS, BATCH), 256, SMEM_ATTN5>>>(qkvh, nullptr, pO, pL, NX, KSPLIT);
    merge_attn<<<dim3(QBY, HEADS, BATCH), 128>>>(pO, pL, attno);
    // 5) output projection + bias + input residual -> d_out
    gemm_fp16<1><<<dim3(DIMC/128, TTOK/128), 256, SMEM_GEMM>>>(attno, wrnd + OFF_PROJW, projb, nullptr,
        TTOK, DIMC, DIMC, x, y, outx, outy);
    // 6) LN2 over d_out
    ln_fast<<<TTOK/8, 256>>>(outx, outy, n2w, n2b, ln2o);
    // 7) fc1 + bias + exact GELU
    gemm_fp16<2><<<dim3(HIDDEN/128, TTOK/128), 256, SMEM_GEMM>>>(ln2o, wrnd + OFF_FC1W, fc1bb, fc1o,
        TTOK, HIDDEN, DIMC, nullptr, nullptr, nullptr, nullptr);
    // 8) fc2 + bias + residual (in place on d_out)
    gemm_fp16<3><<<dim3(DIMC/128, TTOK/128), 256, SMEM_GEMM>>>(fc1o, wrnd + OFF_FC2W, fc2b, nullptr,
        TTOK, DIMC, HIDDEN, nullptr, nullptr, outx, outy);
}

// round 13
// speedup vs baseline: 1.4168x; 1.4168x over previous
#include <cuda_runtime.h>
#include <cuda_fp16.h>
#include <math.h>
#include <stdint.h>

// ---------------- problem constants ----------------
#define DIMC   384
#define HEADS  6
#define HD     64
#define HIDDEN 1536
#define BATCH  4
#define NX     2048
#define NY     256
#define MTOK   2304
#define TTOK   (BATCH*MTOK)          // 9216
#define QKVN   (3*DIMC)              // 1152
#define ATT_SCALE 0.125f
#define LN_EPS 1e-5f

#define HTS 72                       // half row stride (elements); 144B = 36 u32

// attention smem: K/V double buffers only
#define SMEM_ATTN5 (4*64*HTS*2)      // 36,864 B

// GEMM smem: A/W tiles 128x64 halves, double buffered (no epilogue buffer)
#define GT_BYTES (128*HTS*2)         // 18,432 per tile buffer
#define SMEM_GEMM (4*GT_BYTES)       // 73,728 B

#define NSPLIT 4
#define KSPLIT (MTOK/NSPLIT)         // 576
#define QBY    (NY/128)              // 2

// weight scratch offsets (half weights)
#define OFF_QKVW 0
#define OFF_PROJW (QKVN*DIMC)
#define OFF_FC1W  (OFF_PROJW + DIMC*DIMC)
#define OFF_FC2W  (OFF_FC1W + HIDDEN*DIMC)
#define W_TOTAL   (OFF_FC2W + DIMC*HIDDEN)

// ---------------- scratch ----------------
__device__ __half g_catln[TTOK*DIMC];
__device__ __half g_qkvh [TTOK*QKVN];
__device__ __half g_attno[TTOK*DIMC];
__device__ __half g_ln2  [TTOK*DIMC];
__device__ __half g_fc1  [TTOK*HIDDEN];
__device__ __half g_wrnd [W_TOTAL];
__device__ float  g_pO   [BATCH*HEADS*QBY*NSPLIT*128*64];
__device__ float  g_pL   [BATCH*HEADS*QBY*NSPLIT*128];

// ---------------- helpers ----------------
__device__ __forceinline__ void cp16(void* smem, const void* gmem) {
    uint32_t s = (uint32_t)__cvta_generic_to_shared(smem);
    asm volatile("cp.async.cg.shared.global [%0], [%1], 16;" :: "r"(s), "l"(gmem));
}
#define CP_COMMIT() asm volatile("cp.async.commit_group;")
#define CP_WAIT0()  asm volatile("cp.async.wait_group 0;")

__device__ __forceinline__ void mma16816(float* c, const uint32_t* a, uint32_t b0, uint32_t b1) {
    asm volatile(
        "mma.sync.aligned.m16n8k16.row.col.f32.f16.f16.f32 "
        "{%0,%1,%2,%3},{%4,%5,%6,%7},{%8,%9},{%0,%1,%2,%3};"
        : "+f"(c[0]), "+f"(c[1]), "+f"(c[2]), "+f"(c[3])
        : "r"(a[0]), "r"(a[1]), "r"(a[2]), "r"(a[3]), "r"(b0), "r"(b1));
}
__device__ __forceinline__ uint32_t pack_h2(float x, float y) {
    __half2 h = __floats2half2_rn(x, y);
    return *(uint32_t*)&h;
}
__device__ __forceinline__ float gelu_erf(float x) {
    return 0.5f * x * (1.0f + erff(x * 0.70710678118654752f));
}

// ---------------- weight pre-rounding to fp16 ----------------
__global__ void round_weights(const float* __restrict__ qkvw, const float* __restrict__ projw,
                              const float* __restrict__ fc1w, const float* __restrict__ fc2w,
                              __half* __restrict__ dst)
{
    int stride = gridDim.x * blockDim.x;
    int i0 = blockIdx.x * blockDim.x + threadIdx.x;
    for (int i = i0; i < QKVN*DIMC;   i += stride) dst[OFF_QKVW + i]  = __float2half(qkvw[i]);
    for (int i = i0; i < DIMC*DIMC;   i += stride) dst[OFF_PROJW + i] = __float2half(projw[i]);
    for (int i = i0; i < HIDDEN*DIMC; i += stride) dst[OFF_FC1W + i]  = __float2half(fc1w[i]);
    for (int i = i0; i < DIMC*HIDDEN; i += stride) dst[OFF_FC2W + i]  = __float2half(fc2w[i]);
}

// ---------------- LayerNorm: 1 warp per token ----------------
__global__ void __launch_bounds__(256) ln_fast(
    const float* __restrict__ px, const float* __restrict__ py,
    const float* __restrict__ w,  const float* __restrict__ bsh,
    __half* __restrict__ out)
{
    int wi = threadIdx.x >> 5, lane = threadIdx.x & 31;
    int t  = blockIdx.x*8 + wi;
    int bb = t / MTOK, pos = t - bb*MTOK;
    const float* src = (pos < NX)
        ? px + (size_t)(bb*NX + pos)*DIMC
        : py + (size_t)(bb*NY + pos - NX)*DIMC;

    float4 v[3];
    float s = 0.f, sq = 0.f;
    #pragma unroll
    for (int i = 0; i < 3; i++) {
        v[i] = ((const float4*)src)[lane + 32*i];
        s  += v[i].x + v[i].y + v[i].z + v[i].w;
        sq += v[i].x*v[i].x + v[i].y*v[i].y + v[i].z*v[i].z + v[i].w*v[i].w;
    }
    #pragma unroll
    for (int o = 16; o; o >>= 1) {
        s  += __shfl_xor_sync(0xffffffffu, s,  o);
        sq += __shfl_xor_sync(0xffffffffu, sq, o);
    }
    float mean = s * (1.0f/DIMC);
    float inv  = rsqrtf(sq * (1.0f/DIMC) - mean*mean + LN_EPS);

    uint32_t* op = (uint32_t*)(out + (size_t)t*DIMC);
    #pragma unroll
    for (int i = 0; i < 3; i++) {
        int idx4 = lane + 32*i;
        float4 ww = ((const float4*)w)[idx4];
        float4 bb4 = ((const float4*)bsh)[idx4];
        op[2*idx4]   = pack_h2((v[i].x-mean)*inv*ww.x + bb4.x, (v[i].y-mean)*inv*ww.y + bb4.y);
        op[2*idx4+1] = pack_h2((v[i].z-mean)*inv*ww.z + bb4.z, (v[i].w-mean)*inv*ww.w + bb4.w);
    }
}

// ---------------- pairwise epilogue for fp32-residual outputs ----------------
template<int EPI>
__device__ __forceinline__ void epi_res2(int m, int n, float v0, float v1,
    const float* __restrict__ bias,
    const float* __restrict__ resx, const float* __restrict__ resy,
    float* __restrict__ outx, float* __restrict__ outy)
{
    float2 bv = *(const float2*)(bias + n);
    int bb  = m / MTOK;
    int pos = m - bb * MTOK;
    size_t idx;
    float* outp;
    const float* resp;
    if (pos < NX) {
        idx = ((size_t)(bb*NX + pos))*DIMC + n;
        outp = outx;
        resp = (EPI == 1) ? resx : outx;
    } else {
        idx = ((size_t)(bb*NY + pos - NX))*DIMC + n;
        outp = outy;
        resp = (EPI == 1) ? resy : outy;
    }
    float2 r = *(const float2*)(resp + idx);
    float2 o = make_float2(v0 + bv.x + r.x, v1 + bv.y + r.y);
    *(float2*)(outp + idx) = o;
}

// ---------------- raw-PTX fp16 GEMM: register-direct epilogue ----------------
// C[M,N] = A[M,K] * W[N,K]^T. Block 128x128, 8 warps (4x2), warp 32x64,
// k-tile 64 cp.async double-buffered. acc[2][8][4] in registers.
// EPI 0: fp16 store (qkv) | 1: +bias+input residual fp32 | 2: +bias+GELU fp16 | 3: +bias+out residual fp32
template<int EPI>
__global__ void __launch_bounds__(256, 2) gemm_raw(
    const __half* __restrict__ A, const __half* __restrict__ W,
    const float* __restrict__ bias, __half* __restrict__ C,
    int M, int N, int K,
    const float* __restrict__ resx, const float* __restrict__ resy,
    float* __restrict__ outx, float* __restrict__ outy)
{
    extern __shared__ __align__(16) char dsm[];
    __half* Ab[2] = { (__half*)(dsm),              (__half*)(dsm + GT_BYTES)   };
    __half* Wb[2] = { (__half*)(dsm + 2*GT_BYTES), (__half*)(dsm + 3*GT_BYTES) };

    int tid = threadIdx.x;
    int w = tid >> 5, lane = tid & 31;
    int g = lane >> 2, t = lane & 3;
    int wm = w >> 1, wn = w & 1;
    int m0 = blockIdx.y << 7;
    int n0 = blockIdx.x << 7;

    float acc[2][8][4];
    #pragma unroll
    for (int i = 0; i < 2; i++)
        #pragma unroll
        for (int j = 0; j < 8; j++)
            #pragma unroll
            for (int c = 0; c < 4; c++) acc[i][j][c] = 0.f;

    int T = K >> 6;
    {   // stage tile 0
        #pragma unroll
        for (int i = 0; i < 4; i++) {
            int idx = tid + i*256;
            int row = idx >> 3, c8 = (idx & 7) << 3;
            cp16(Ab[0] + row*HTS + c8, A + (size_t)(m0+row)*K + c8);
            cp16(Wb[0] + row*HTS + c8, W + (size_t)(n0+row)*K + c8);
        }
        CP_COMMIT();
    }

    for (int tt = 0; tt < T; tt++) {
        CP_WAIT0();
        __syncthreads();
        if (tt + 1 < T) {
            int k0 = (tt+1) << 6;
            __half* An = Ab[(tt+1)&1];
            __half* Wn = Wb[(tt+1)&1];
            #pragma unroll
            for (int i = 0; i < 4; i++) {
                int idx = tid + i*256;
                int row = idx >> 3, c8 = (idx & 7) << 3;
                cp16(An + row*HTS + c8, A + (size_t)(m0+row)*K + k0 + c8);
                cp16(Wn + row*HTS + c8, W + (size_t)(n0+row)*K + k0 + c8);
            }
            CP_COMMIT();
        }
        const uint32_t* Au = (const uint32_t*)Ab[tt&1];   // row stride 36 u32
        const uint32_t* Wu = (const uint32_t*)Wb[tt&1];

        #pragma unroll
        for (int ks = 0; ks < 4; ks++) {
            int ko = ks << 3;
            uint32_t a0[4], a1[4];
            {
                int ar = (wm*32 + g)*36 + ko + t;
                a0[0] = Au[ar];          a0[1] = Au[ar + 8*36];
                a0[2] = Au[ar + 4];      a0[3] = Au[ar + 8*36 + 4];
                int ar1 = ar + 16*36;
                a1[0] = Au[ar1];         a1[1] = Au[ar1 + 8*36];
                a1[2] = Au[ar1 + 4];     a1[3] = Au[ar1 + 8*36 + 4];
            }
            #pragma unroll
            for (int j = 0; j < 8; j++) {
                int br = (wn*64 + 8*j + g)*36 + ko + t;
                uint32_t b0 = Wu[br], b1 = Wu[br + 4];
                mma16816(acc[0][j], a0, b0, b1);
                mma16816(acc[1][j], a1, b0, b1);
            }
        }
        __syncthreads();
    }

    // register-direct epilogue (layout: c0,c1 -> row g, cols 2t,2t+1; c2,c3 -> row g+8)
    #pragma unroll
    for (int i = 0; i < 2; i++) {
        int row0 = m0 + wm*32 + i*16 + g;
        int row1 = row0 + 8;
        #pragma unroll
        for (int j = 0; j < 8; j++) {
            int col = n0 + wn*64 + j*8 + 2*t;
            float c0 = acc[i][j][0], c1 = acc[i][j][1];
            float c2 = acc[i][j][2], c3 = acc[i][j][3];
            if (EPI == 0) {
                *(uint32_t*)(C + (size_t)row0*N + col) = pack_h2(c0, c1);
                *(uint32_t*)(C + (size_t)row1*N + col) = pack_h2(c2, c3);
            } else if (EPI == 2) {
                float2 bv = *(const float2*)(bias + col);
                *(uint32_t*)(C + (size_t)row0*N + col) =
                    pack_h2(gelu_erf(c0 + bv.x), gelu_erf(c1 + bv.y));
                *(uint32_t*)(C + (size_t)row1*N + col) =
                    pack_h2(gelu_erf(c2 + bv.x), gelu_erf(c3 + bv.y));
            } else {
                epi_res2<EPI>(row0, col, c0, c1, bias, resx, resy, outx, outy);
                epi_res2<EPI>(row1, col, c2, c3, bias, resx, resy, outx, outy);
            }
        }
    }
}

// ---------------- attention v5 (R11-proven): raw PTX mma, register S/P/O ----------------
template<bool SPLIT>
__global__ void __launch_bounds__(256, 2) attn_v5(
    const __half* __restrict__ qkvh, __half* __restrict__ attno,
    float* __restrict__ pO, float* __restrict__ pL,
    int q_base, int klen)
{
    extern __shared__ __align__(16) char dsm[];
    __half* Kb[2] = { (__half*)(dsm),               (__half*)(dsm + 64*HTS*2)   };
    __half* Vb[2] = { (__half*)(dsm + 2*64*HTS*2),  (__half*)(dsm + 3*64*HTS*2) };

    int tid = threadIdx.x, w = tid >> 5, lane = tid & 31;
    int g = lane >> 2, t = lane & 3;
    int h = blockIdx.y, b = blockIdx.z;
    int qb, sp;
    if (SPLIT) { qb = blockIdx.x >> 2; sp = blockIdx.x & 3; }
    else       { qb = blockIdx.x;      sp = 0; }
    int q0   = q_base + (qb << 7);
    int koff = SPLIT ? sp * klen : 0;

    uint32_t qa[4][4];
    {
        const __half* qrow0 = qkvh + (size_t)(b*MTOK + q0 + w*16 + g)*QKVN + h*HD;
        const __half* qrow1 = qrow0 + 8*QKVN;
        #pragma unroll
        for (int c = 0; c < 4; c++) {
            qa[c][0] = *(const uint32_t*)(qrow0 + 16*c     + 2*t);
            qa[c][1] = *(const uint32_t*)(qrow1 + 16*c     + 2*t);
            qa[c][2] = *(const uint32_t*)(qrow0 + 16*c + 8 + 2*t);
            qa[c][3] = *(const uint32_t*)(qrow1 + 16*c + 8 + 2*t);
        }
    }

    float oac[8][4];
    #pragma unroll
    for (int j = 0; j < 8; j++)
        #pragma unroll
        for (int c = 0; c < 4; c++) oac[j][c] = 0.f;
    float rs0 = 0.f, rs1 = 0.f;

    const __half* kbase = qkvh + ((size_t)b*MTOK)*QKVN + DIMC   + h*HD;
    const __half* vbase = qkvh + ((size_t)b*MTOK)*QKVN + 2*DIMC + h*HD;

    int T = klen >> 6;
    {
        #pragma unroll
        for (int i = 0; i < 2; i++) {
            int idx = tid + i*256;
            int row = idx >> 3, c8 = (idx & 7) << 3;
            cp16(Kb[0] + row*HTS + c8, kbase + (size_t)(koff+row)*QKVN + c8);
            cp16(Vb[0] + row*HTS + c8, vbase + (size_t)(koff+row)*QKVN + c8);
        }
        CP_COMMIT();
    }

    for (int it = 0; it < T; it++) {
        CP_WAIT0();
        __syncthreads();
        if (it + 1 < T) {
            int kt = koff + ((it+1) << 6);
            __half* Kn = Kb[(it+1)&1];
            __half* Vn = Vb[(it+1)&1];
            #pragma unroll
            for (int i = 0; i < 2; i++) {
                int idx = tid + i*256;
                int row = idx >> 3, c8 = (idx & 7) << 3;
                cp16(Kn + row*HTS + c8, kbase + (size_t)(kt+row)*QKVN + c8);
                cp16(Vn + row*HTS + c8, vbase + (size_t)(kt+row)*QKVN + c8);
            }
            CP_COMMIT();
        }
        const uint32_t* Ku = (const uint32_t*)Kb[it&1];
        __half* Vs = Vb[it&1];

        uint32_t ph[8][2];
        #pragma unroll
        for (int j = 0; j < 8; j++) {
            float sc[4] = {0.f, 0.f, 0.f, 0.f};
            int krow = (8*j + g)*36 + t;
            #pragma unroll
            for (int c = 0; c < 4; c++)
                mma16816(sc, qa[c], Ku[krow + 8*c], Ku[krow + 8*c + 4]);
            float e0 = __expf(sc[0]*ATT_SCALE);
            float e1 = __expf(sc[1]*ATT_SCALE);
            float e2 = __expf(sc[2]*ATT_SCALE);
            float e3 = __expf(sc[3]*ATT_SCALE);
            rs0 += e0 + e1;
            rs1 += e2 + e3;
            ph[j][0] = pack_h2(e0, e1);
            ph[j][1] = pack_h2(e2, e3);
        }

        #pragma unroll
        for (int kc = 0; kc < 4; kc++) {
            uint32_t af[4] = { ph[2*kc][0], ph[2*kc][1], ph[2*kc+1][0], ph[2*kc+1][1] };
            #pragma unroll
            for (int jd = 0; jd < 8; jd += 2) {
                int row = 16*kc + ((lane >> 3) & 1)*8 + (lane & 7);
                int col = 8*jd + ((lane >> 4) << 3);
                uint32_t addr = (uint32_t)__cvta_generic_to_shared(Vs + row*HTS + col);
                uint32_t v0, v1, v2, v3;
                asm volatile(
                    "ldmatrix.sync.aligned.m8n8.x4.trans.shared.b16 {%0,%1,%2,%3}, [%4];"
                    : "=r"(v0), "=r"(v1), "=r"(v2), "=r"(v3) : "r"(addr));
                mma16816(oac[jd],   af, v0, v1);
                mma16816(oac[jd+1], af, v2, v3);
            }
        }
    }

    rs0 += __shfl_xor_sync(0xffffffffu, rs0, 1);
    rs0 += __shfl_xor_sync(0xffffffffu, rs0, 2);
    rs1 += __shfl_xor_sync(0xffffffffu, rs1, 1);
    rs1 += __shfl_xor_sync(0xffffffffu, rs1, 2);

    if (SPLIT) {
        int pidx = ((b*HEADS + h)*QBY + qb)*NSPLIT + sp;
        float* dst0 = pO + (size_t)pidx*(128*64) + (w*16 + g)*64;
        float* dst1 = dst0 + 8*64;
        #pragma unroll
        for (int jd = 0; jd < 8; jd++) {
            int col = 8*jd + 2*t;
            *(float2*)(dst0 + col) = make_float2(oac[jd][0], oac[jd][1]);
            *(float2*)(dst1 + col) = make_float2(oac[jd][2], oac[jd][3]);
        }
        if (t == 0) {
            pL[pidx*128 + w*16 + g]     = rs0;
            pL[pidx*128 + w*16 + g + 8] = rs1;
        }
    } else {
        float inv0 = 1.f / rs0;
        float inv1 = 1.f / rs1;
        __half* orow0 = attno + (size_t)(b*MTOK + q0 + w*16 + g)*DIMC + h*HD;
        __half* orow1 = orow0 + 8*DIMC;
        #pragma unroll
        for (int jd = 0; jd < 8; jd++) {
            int col = 8*jd + 2*t;
            *(uint32_t*)(orow0 + col) = pack_h2(oac[jd][0]*inv0, oac[jd][1]*inv0);
            *(uint32_t*)(orow1 + col) = pack_h2(oac[jd][2]*inv1, oac[jd][3]*inv1);
        }
    }
}

// ---------------- merge split-K partials ----------------
__global__ void __launch_bounds__(128) merge_attn(
    const float* __restrict__ pO, const float* __restrict__ pL,
    __half* __restrict__ attno)
{
    int qb = blockIdx.x, h = blockIdx.y, b = blockIdx.z;
    int r = threadIdx.x;
    int base = ((b*HEADS + h)*QBY + qb)*NSPLIT;

    float L = 0.f;
    #pragma unroll
    for (int s = 0; s < NSPLIT; s++) L += pL[(base+s)*128 + r];
    float inv = 1.f / L;

    int qi = NX + (qb << 7) + r;
    __half* op = attno + ((size_t)(b*MTOK + qi))*DIMC + h*HD;
    #pragma unroll 4
    for (int c = 0; c < 64; c++) {
        float o = 0.f;
        #pragma unroll
        for (int s = 0; s < NSPLIT; s++)
            o += pO[(size_t)(base+s)*(128*64) + r*64 + c];
        op[c] = __float2half(o * inv);
    }
}

// ---------------- launch ----------------
extern "C" void kernel_launch(void* const* d_in, const int* in_sizes, int n_in,
                              void* d_out, int out_size)
{
    const float* x     = (const float*)d_in[0];
    const float* y     = (const float*)d_in[1];
    const float* n1w   = (const float*)d_in[2];
    const float* n1b   = (const float*)d_in[3];
    const float* n2w   = (const float*)d_in[4];
    const float* n2b   = (const float*)d_in[5];
    const float* qkvw  = (const float*)d_in[6];
    const float* projw = (const float*)d_in[7];
    const float* projb = (const float*)d_in[8];
    const float* fc1w  = (const float*)d_in[9];
    const float* fc1bb = (const float*)d_in[10];
    const float* fc2w  = (const float*)d_in[11];
    const float* fc2b  = (const float*)d_in[12];
    (void)in_sizes; (void)n_in; (void)out_size;

    float* outx = (float*)d_out;
    float* outy = outx + (size_t)BATCH*NX*DIMC;

    __half *catln, *qkvh, *attno, *ln2o, *fc1o, *wrnd;
    float *pO, *pL;
    cudaGetSymbolAddress((void**)&catln, g_catln);
    cudaGetSymbolAddress((void**)&qkvh,  g_qkvh);
    cudaGetSymbolAddress((void**)&attno, g_attno);
    cudaGetSymbolAddress((void**)&ln2o,  g_ln2);
    cudaGetSymbolAddress((void**)&fc1o,  g_fc1);
    cudaGetSymbolAddress((void**)&wrnd,  g_wrnd);
    cudaGetSymbolAddress((void**)&pO,    g_pO);
    cudaGetSymbolAddress((void**)&pL,    g_pL);

    cudaFuncSetAttribute(gemm_raw<0>, cudaFuncAttributeMaxDynamicSharedMemorySize, SMEM_GEMM);
    cudaFuncSetAttribute(gemm_raw<1>, cudaFuncAttributeMaxDynamicSharedMemorySize, SMEM_GEMM);
    cudaFuncSetAttribute(gemm_raw<2>, cudaFuncAttributeMaxDynamicSharedMemorySize, SMEM_GEMM);
    cudaFuncSetAttribute(gemm_raw<3>, cudaFuncAttributeMaxDynamicSharedMemorySize, SMEM_GEMM);

    // 0) pre-round weights to fp16
    round_weights<<<256, 256>>>(qkvw, projw, fc1w, fc2w, wrnd);
    // 1) LN1 over concat(x, y)
    ln_fast<<<TTOK/8, 256>>>(x, y, n1w, n1b, catln);
    // 2) fused QKV GEMM
    gemm_raw<0><<<dim3(QKVN/128, TTOK/128), 256, SMEM_GEMM>>>(catln, wrnd + OFF_QKVW, nullptr, qkvh,
        TTOK, QKVN, DIMC, nullptr, nullptr, nullptr, nullptr);
    // 3) x self-attention
    attn_v5<false><<<dim3(NX/128, HEADS, BATCH), 256, SMEM_ATTN5>>>(qkvh, attno, nullptr, nullptr, 0, NX);
    // 4) y cross-attention: split-K x4 + merge
    attn_v5<true><<<dim3(QBY*NSPLIT, HEADS, BATCH), 256, SMEM_ATTN5>>>(qkvh, nullptr, pO, pL, NX, KSPLIT);
    merge_attn<<<dim3(QBY, HEADS, BATCH), 128>>>(pO, pL, attno);
    // 5) output projection + bias + input residual -> d_out
    gemm_raw<1><<<dim3(DIMC/128, TTOK/128), 256, SMEM_GEMM>>>(attno, wrnd + OFF_PROJW, projb, nullptr,
        TTOK, DIMC, DIMC, x, y, outx, outy);
    // 6) LN2 over d_out
    ln_fast<<<TTOK/8, 256>>>(outx, outy, n2w, n2b, ln2o);
    // 7) fc1 + bias + exact GELU
    gemm_raw<2><<<dim3(HIDDEN/128, TTOK/128), 256, SMEM_GEMM>>>(ln2o, wrnd + OFF_FC1W, fc1bb, fc1o,
        TTOK, HIDDEN, DIMC, nullptr, nullptr, nullptr, nullptr);
    // 8) fc2 + bias + residual (in place on d_out)
    gemm_raw<3><<<dim3(DIMC/128, TTOK/128), 256, SMEM_GEMM>>>(fc1o, wrnd + OFF_FC2W, fc2b, nullptr,
        TTOK, DIMC, HIDDEN, nullptr, nullptr, outx, outy);
}